// round 16
// baseline (speedup 1.0000x reference)
#include <cuda_runtime.h>
#include <cstdint>

#define N_ 50000
#define K_ 32
#define D_ 128
#define EPS_ 1e-12f
#define WARPS_PER_BLOCK 8
#define THREADS_ (WARPS_PER_BLOCK * 32)
#define NBLOCKS_ ((N_ + WARPS_PER_BLOCK - 1) / WARPS_PER_BLOCK)   // 6250
#define ROWB_ 392   // packed row: 256B hi | 128B lo | 4B norm | 4B pad

__device__ uint8_t  g_pack[(size_t)N_ * ROWB_];   // 19.6 MB
__device__ double   g_block_partials[NBLOCKS_];
__device__ unsigned g_ticket = 0;                 // returns to 0 each run (graph-replay safe)

// Warp-per-row prep: round fp32 to 24 bits, store [hi16 x128 | lo8 x128 | ||b_q||^2].
__global__ __launch_bounds__(THREADS_)
void snl_prep_kernel(const float* __restrict__ emb) {
    const int warp = threadIdx.x >> 5;
    const int lane = threadIdx.x & 31;
    const int i = blockIdx.x * WARPS_PER_BLOCK + warp;

    const uint4 y = reinterpret_cast<const uint4*>(emb + (size_t)i * D_)[lane];
    const unsigned r0 = y.x + 0x80u, r1 = y.y + 0x80u;
    const unsigned r2 = y.z + 0x80u, r3 = y.w + 0x80u;

    // quantized values (exactly what the main kernel will reconstruct)
    const float q0 = __uint_as_float(r0 & 0xFFFFFF00u);
    const float q1 = __uint_as_float(r1 & 0xFFFFFF00u);
    const float q2 = __uint_as_float(r2 & 0xFFFFFF00u);
    const float q3 = __uint_as_float(r3 & 0xFFFFFF00u);
    float nrm = q0 * q0;
    nrm = fmaf(q1, q1, nrm);
    nrm = fmaf(q2, q2, nrm);
    nrm = fmaf(q3, q3, nrm);
    #pragma unroll
    for (int o = 16; o; o >>= 1) nrm += __shfl_xor_sync(0xffffffffu, nrm, o);

    ushort4 h;
    h.x = (unsigned short)(r0 >> 16); h.y = (unsigned short)(r1 >> 16);
    h.z = (unsigned short)(r2 >> 16); h.w = (unsigned short)(r3 >> 16);
    uchar4 l;
    l.x = (unsigned char)(r0 >> 8); l.y = (unsigned char)(r1 >> 8);
    l.z = (unsigned char)(r2 >> 8); l.w = (unsigned char)(r3 >> 8);

    uint8_t* row = g_pack + (size_t)i * ROWB_;
    *reinterpret_cast<ushort4*>(row + 8 * lane) = h;        // hi plane [0,256)
    *reinterpret_cast<uchar4*>(row + 256 + 4 * lane) = l;   // lo plane [256,384)
    if (lane == 0)
        *reinterpret_cast<float*>(row + 384) = nrm;         // ||b_q||^2
}

__global__ __launch_bounds__(THREADS_, 5)
void snl_main_kernel(const float* __restrict__ emb,
                     const float* __restrict__ p,
                     const int* __restrict__ anchor,
                     float* __restrict__ out /* [0]=loss, [1..]=q */) {
    __shared__ double loss_s[WARPS_PER_BLOCK];
    __shared__ double red_s[THREADS_];
    __shared__ bool   is_last;

    const int warp = threadIdx.x >> 5;
    const int lane = threadIdx.x & 31;
    const int i = blockIdx.x * WARPS_PER_BLOCK + warp;   // 6250*8 == 50000 exactly
    float* __restrict__ out_q = out + 1;

    const int j_mine = anchor[(size_t)i * K_ + lane];    // lane k owns anchor k

    // hoisted scattered norm load: overlaps everything below (R11-validated)
    const float nb = *reinterpret_cast<const float*>(g_pack + (size_t)j_mine * ROWB_ + 384);

    // anchor owned by lane l after the folds (pure lane function — hoist p load)
    const int acol = 4 * (lane & 7) + 2 * ((lane >> 3) & 1) + ((lane >> 4) & 1);
    const float pv = p[(size_t)i * K_ + acol];

    // yi exact, pre-scaled by 2: dot partial accumulates 2*a.b directly
    const float4 a0 = reinterpret_cast<const float4*>(emb + (size_t)i * D_)[lane];
    const float4 a = make_float4(2.0f * a0.x, 2.0f * a0.y, 2.0f * a0.z, 2.0f * a0.w);

    const bool hi16 = (lane & 16) != 0;
    const bool hi8  = (lane & 8) != 0;

    auto fold = [&](float lo_v, float hi_v, bool up, int s) -> float {
        const float send = up ? lo_v : hi_v;
        return (up ? hi_v : lo_v) + __shfl_xor_sync(0xffffffffu, send, s);
    };

    // load the 4 anchors of group g into a register buffer (uniform addresses)
    auto loadgrp = [&](int g, uint2* hw, unsigned* lw) {
        #pragma unroll
        for (int h = 0; h < 4; h++) {
            const int jr = __shfl_sync(0xffffffffu, j_mine, 4 * g + h);
            const uint8_t* row = g_pack + (size_t)jr * ROWB_;
            hw[h] = *reinterpret_cast<const uint2*>(row + 8 * lane);
            lw[h] = *reinterpret_cast<const unsigned*>(row + 256 + 4 * lane);
        }
    };

    // decode 4 anchors (dot partials: 4 PRMT + 4 FP each) and fold to one register
    auto decode_fold = [&](const uint2* hw, const unsigned* lw) -> float {
        float pp[4];
        #pragma unroll
        for (int h = 0; h < 4; h++) {
            // fp32 bytes [b3 b2 b1 b0] = [hiB1, hiB0, lo8, junk(0 from perm of hw)]
            const float bx = __uint_as_float(__byte_perm(hw[h].x, lw[h], 0x1044) & 0xFFFFFF00u);
            const float by = __uint_as_float(__byte_perm(hw[h].x, lw[h], 0x3255) & 0xFFFFFF00u);
            const float bz = __uint_as_float(__byte_perm(hw[h].y, lw[h], 0x1066) & 0xFFFFFF00u);
            const float bw = __uint_as_float(__byte_perm(hw[h].y, lw[h], 0x3277) & 0xFFFFFF00u);
            float pr = a.x * bx;
            pr = fmaf(a.y, by, pr);
            pr = fmaf(a.z, bz, pr);
            pr = fmaf(a.w, bw, pr);
            pp[h] = pr;
        }
        const float u0 = fold(pp[0], pp[1], hi16, 16);   // idx bit0 = b16
        const float u1 = fold(pp[2], pp[3], hi16, 16);
        return fold(u0, u1, hi8, 8);                     // idx bit1 = b8
    };

    // Software-pipelined group loop (depth 2)
    float w[K_ / 4];
    uint2    hwb[2][4];
    unsigned lwb[2][4];
    loadgrp(0, hwb[0], lwb[0]);
    #pragma unroll
    for (int g = 0; g < K_ / 4; g++) {
        if (g < K_ / 4 - 1)
            loadgrp(g + 1, hwb[(g + 1) & 1], lwb[(g + 1) & 1]);
        w[g] = decode_fold(hwb[g & 1], lwb[g & 1]);
    }

    // Recursive halving on 8 values: 7 shuffles; lane l ends with anchor acol(l).
    #pragma unroll
    for (int s = 4; s >= 1; s >>= 1) {
        const bool upper = (lane & s) != 0;
        #pragma unroll
        for (int k = 0; k < s; k++) {
            const float send = upper ? w[k] : w[k + s];
            const float recv = __shfl_xor_sync(0xffffffffu, send, s);
            w[k] = (upper ? w[k + s] : w[k]) + recv;
        }
    }

    // shifted logit: s = 2*a.b_q - ||b_q||^2  ==  ||a||^2 - |a - b_q|^2
    // (||a||^2 is constant over the row -> cancels in log-softmax; identity is EXACT)
    const float sc = w[0] - __shfl_sync(0xffffffffu, nb, acol);

    // softmax over the 32 lanes
    float m = sc;
    #pragma unroll
    for (int o = 16; o; o >>= 1) m = fmaxf(m, __shfl_xor_sync(0xffffffffu, m, o));
    const float e = __expf(sc - m);
    float sum = e;
    #pragma unroll
    for (int o = 16; o; o >>= 1) sum += __shfl_xor_sync(0xffffffffu, sum, o);
    const float lse = m + __logf(sum);
    const float logq = sc - lse;
    const float q = __expf(logq);

    out_q[(size_t)i * K_ + acol] = q;

    float contrib = pv * (__logf(pv + EPS_) - logq);
    #pragma unroll
    for (int o = 16; o; o >>= 1) contrib += __shfl_xor_sync(0xffffffffu, contrib, o);
    if (lane == 0) loss_s[warp] = (double)contrib;
    __syncthreads();

    if (threadIdx.x == 0) {
        double blk = 0.0;
        #pragma unroll
        for (int w2 = 0; w2 < WARPS_PER_BLOCK; w2++) blk += loss_s[w2];
        g_block_partials[blockIdx.x] = blk;
        __threadfence();
        unsigned t = atomicAdd(&g_ticket, 1u);
        is_last = (t == (unsigned)(NBLOCKS_ - 1));
    }
    __syncthreads();

    if (is_last) {
        __threadfence();
        double acc = 0.0;
        for (int b = threadIdx.x; b < NBLOCKS_; b += THREADS_)
            acc += g_block_partials[b];
        red_s[threadIdx.x] = acc;
        __syncthreads();
        #pragma unroll
        for (int o = THREADS_ / 2; o; o >>= 1) {
            if (threadIdx.x < o) red_s[threadIdx.x] += red_s[threadIdx.x + o];
            __syncthreads();
        }
        if (threadIdx.x == 0) {
            out[0] = (float)(red_s[0] / (double)N_);
            g_ticket = 0;
        }
    }
}

extern "C" void kernel_launch(void* const* d_in, const int* in_sizes, int n_in,
                              void* d_out, int out_size) {
    const float* emb    = (const float*)d_in[0];  // output_embedding [N, D] f32
    const float* p      = (const float*)d_in[1];  // input_similarity [N, K] f32
    const int*   anchor = (const int*)d_in[2];    // anchor_idx [N, K] int32
    float* out = (float*)d_out;                   // [0]=loss, [1..]=q row-major

    snl_prep_kernel<<<NBLOCKS_, THREADS_>>>(emb);
    snl_main_kernel<<<NBLOCKS_, THREADS_>>>(emb, p, anchor, out);
}

// round 17
// speedup vs baseline: 1.1084x; 1.1084x over previous
#include <cuda_runtime.h>

#define N_ 50000
#define K_ 32
#define D_ 128
#define EPS_ 1e-12f
#define WARPS_PER_BLOCK 8
#define THREADS_ (WARPS_PER_BLOCK * 32)
#define NBLOCKS_ ((N_ + WARPS_PER_BLOCK - 1) / WARPS_PER_BLOCK)   // 6250

__device__ double   g_block_partials[NBLOCKS_];
__device__ unsigned g_ticket = 0;   // returns to 0 at end of every run (graph-replay safe)

__global__ __launch_bounds__(THREADS_, 6)
void snl_main_kernel(const float* __restrict__ emb,
                     const float* __restrict__ p,
                     const int* __restrict__ anchor,
                     float* __restrict__ out /* [0]=loss, [1..]=q */) {
    __shared__ double loss_s[WARPS_PER_BLOCK];
    __shared__ double red_s[THREADS_];
    __shared__ bool   is_last;

    const int warp = threadIdx.x >> 5;
    const int lane = threadIdx.x & 31;
    const int i = blockIdx.x * WARPS_PER_BLOCK + warp;   // 6250*8 == 50000 exactly
    float* __restrict__ out_q = out + 1;

    // anchor owned by lane l after the folds (pure lane function) — hoist p load
    const int acol = 4 * (lane & 7) + 2 * ((lane >> 3) & 1) + ((lane >> 4) & 1);
    const float pv = p[(size_t)i * K_ + acol];

    // lane k owns anchor k's index (used only for broadcasts)
    const int j_mine = anchor[(size_t)i * K_ + lane];

    // yi: lane t holds elements [4t, 4t+4) of row i (coalesced 512B load)
    const float4 a = reinterpret_cast<const float4*>(emb + (size_t)i * D_)[lane];

    const bool hi16 = (lane & 16) != 0;
    const bool hi8  = (lane & 8) != 0;

    // 4-way folded partials: w[g] covers anchors 4g..4g+3 (8 live registers).
    float w[K_ / 4];
    #pragma unroll
    for (int g = 0; g < K_ / 4; g++) {
        const int jr0 = __shfl_sync(0xffffffffu, j_mine, 4 * g);
        const int jr1 = __shfl_sync(0xffffffffu, j_mine, 4 * g + 1);
        const int jr2 = __shfl_sync(0xffffffffu, j_mine, 4 * g + 2);
        const int jr3 = __shfl_sync(0xffffffffu, j_mine, 4 * g + 3);
        const float4 b0 = reinterpret_cast<const float4*>(emb + (size_t)jr0 * D_)[lane];
        const float4 b1 = reinterpret_cast<const float4*>(emb + (size_t)jr1 * D_)[lane];
        const float4 b2 = reinterpret_cast<const float4*>(emb + (size_t)jr2 * D_)[lane];
        const float4 b3 = reinterpret_cast<const float4*>(emb + (size_t)jr3 * D_)[lane];

        float dx = a.x - b0.x, dy = a.y - b0.y, dz = a.z - b0.z, dw = a.w - b0.w;
        float p0 = dx * dx; p0 = fmaf(dy, dy, p0); p0 = fmaf(dz, dz, p0); p0 = fmaf(dw, dw, p0);
        dx = a.x - b1.x; dy = a.y - b1.y; dz = a.z - b1.z; dw = a.w - b1.w;
        float p1 = dx * dx; p1 = fmaf(dy, dy, p1); p1 = fmaf(dz, dz, p1); p1 = fmaf(dw, dw, p1);
        dx = a.x - b2.x; dy = a.y - b2.y; dz = a.z - b2.z; dw = a.w - b2.w;
        float p2 = dx * dx; p2 = fmaf(dy, dy, p2); p2 = fmaf(dz, dz, p2); p2 = fmaf(dw, dw, p2);
        dx = a.x - b3.x; dy = a.y - b3.y; dz = a.z - b3.z; dw = a.w - b3.w;
        float p3 = dx * dx; p3 = fmaf(dy, dy, p3); p3 = fmaf(dz, dz, p3); p3 = fmaf(dw, dw, p3);

        // fold pairs across xor-16: low16 keeps even anchor, high16 keeps odd
        float s01 = hi16 ? p0 : p1;
        float u01 = (hi16 ? p1 : p0) + __shfl_xor_sync(0xffffffffu, s01, 16);
        float s23 = hi16 ? p2 : p3;
        float u23 = (hi16 ? p3 : p2) + __shfl_xor_sync(0xffffffffu, s23, 16);
        // fold across xor-8: bit8=0 keeps u01, bit8=1 keeps u23
        float s8 = hi8 ? u01 : u23;
        w[g] = (hi8 ? u23 : u01) + __shfl_xor_sync(0xffffffffu, s8, 8);
    }

    // Recursive halving on 8 values: 7 shuffles; lane l ends with anchor acol(l).
    #pragma unroll
    for (int s = 4; s >= 1; s >>= 1) {
        const bool upper = (lane & s) != 0;
        #pragma unroll
        for (int k = 0; k < s; k++) {
            const float send = upper ? w[k] : w[k + s];
            const float recv = __shfl_xor_sync(0xffffffffu, send, s);
            w[k] = (upper ? w[k + s] : w[k]) + recv;
        }
    }
    const float myd2 = w[0];

    // softmax over the 32 lanes of s = -d2
    const float sc = -myd2;
    float m = sc;
    #pragma unroll
    for (int o = 16; o; o >>= 1) m = fmaxf(m, __shfl_xor_sync(0xffffffffu, m, o));
    const float e = __expf(sc - m);
    float sum = e;
    #pragma unroll
    for (int o = 16; o; o >>= 1) sum += __shfl_xor_sync(0xffffffffu, sum, o);
    const float lse = m + __logf(sum);
    const float logq = sc - lse;
    const float q = __expf(logq);

    out_q[(size_t)i * K_ + acol] = q;

    // KL contribution, warp-reduced
    float contrib = pv * (__logf(pv + EPS_) - logq);
    #pragma unroll
    for (int o = 16; o; o >>= 1) contrib += __shfl_xor_sync(0xffffffffu, contrib, o);
    if (lane == 0) loss_s[warp] = (double)contrib;
    __syncthreads();

    // block partial -> global, take a ticket; last block does the final sum
    if (threadIdx.x == 0) {
        double blk = 0.0;
        #pragma unroll
        for (int w2 = 0; w2 < WARPS_PER_BLOCK; w2++) blk += loss_s[w2];
        g_block_partials[blockIdx.x] = blk;
        __threadfence();
        unsigned t = atomicAdd(&g_ticket, 1u);
        is_last = (t == (unsigned)(NBLOCKS_ - 1));
    }
    __syncthreads();

    if (is_last) {
        __threadfence();   // acquire: see all blocks' partials
        double acc = 0.0;
        for (int b = threadIdx.x; b < NBLOCKS_; b += THREADS_)
            acc += g_block_partials[b];
        red_s[threadIdx.x] = acc;
        __syncthreads();
        #pragma unroll
        for (int o = THREADS_ / 2; o; o >>= 1) {
            if (threadIdx.x < o) red_s[threadIdx.x] += red_s[threadIdx.x + o];
            __syncthreads();
        }
        if (threadIdx.x == 0) {
            out[0] = (float)(red_s[0] / (double)N_);
            g_ticket = 0;   // restore for next graph replay
        }
    }
}

extern "C" void kernel_launch(void* const* d_in, const int* in_sizes, int n_in,
                              void* d_out, int out_size) {
    const float* emb    = (const float*)d_in[0];  // output_embedding [N, D] f32
    const float* p      = (const float*)d_in[1];  // input_similarity [N, K] f32
    const int*   anchor = (const int*)d_in[2];    // anchor_idx [N, K] int32
    float* out = (float*)d_out;                   // [0]=loss, [1..]=q row-major

    snl_main_kernel<<<NBLOCKS_, THREADS_>>>(emb, p, anchor, out);
}